// round 14
// baseline (speedup 1.0000x reference)
#include <cuda_runtime.h>
#include <math.h>

// Problem constants (match reference)
#define T_STEPS 1024
#define B_SIZE  32768
#define G1      50
#define H1      32
#define G2      20

#define KAN_BLOCKS 512                  // producers (dispatched first), 2 betas each
#define SIR_BLOCKS 512                  // consumers
#define NBLOCKS    (KAN_BLOCKS + SIR_BLOCKS)
#define NCH        4                    // beta chunks
#define CH_T       (T_STEPS / NCH)      // 256 steps per chunk
#define PROD_PER_CH (KAN_BLOCKS / NCH)  // 128 producer blocks per chunk

// Device globals (zero-init at load; NEVER reset — monotonic across launches)
__device__ float        g_cbeta[T_STEPS];
__device__ unsigned int g_cnt[NCH * 32];             // per-chunk arrivals, 128B apart
__device__ unsigned int g_blkepoch[SIR_BLOCKS];      // per-consumer epoch

// ---------------------------------------------------------------------------
// Single-kernel role split + chunked pipeline (epoch-monotonic, no resets).
//  Producers (blocks 0..511, dispatched first): warp w computes beta(2p+w)
//    fully warp-locally (factorized layer-2 RBF, 4-way split h-chain), then
//    tid0 fences and RED-arrives on its chunk counter (p>>7). atomicAdd with
//    unused return -> REDG (0.854 cyc/op) — no atomic-ALU storm.
//  Consumers (blocks 512..1023): e = ++g_blkepoch[sbid] (owner-only);
//    beta-independent prologue overlaps producers; per chunk c, spin until
//    g_cnt[c] >= 128*e (monotonic target: stale value 128(e-1) never
//    passes), then scan 256 steps. Only the chunk-0 wait is exposed
//    (~first-128-blocks' single-beta latency); chunks 1-3 are ready ~6us
//    before consumption.
// Residency: 1024 blocks x 64 thr ~ 6.9 blocks/SM (46.6K regs, 28KB smem
// per SM at 104 regs) -> whole grid in one wave; spins cannot deadlock.
// ---------------------------------------------------------------------------
__global__ void __launch_bounds__(64)
fused_role_kernel(const float* __restrict__ t_steps,
                  const float* __restrict__ initial_I,
                  const float* __restrict__ grid1,
                  const float* __restrict__ spline_w1, // [50,32]
                  const float* __restrict__ base_w1,   // [32]
                  const float* __restrict__ grid2,
                  const float* __restrict__ spline_w2, // [32,20]
                  const float* __restrict__ base_w2,   // [32]
                  const float* __restrict__ gamma_param,
                  float* __restrict__ out)
{
    __shared__ float smem_f[CH_T + 2];      // sir: beta chunk | kan: scratch

    const int tid  = threadIdx.x;
    const int w    = tid >> 5;
    const int lane = tid & 31;

    if (blockIdx.x < KAN_BLOCKS) {
        // ============ PRODUCER: beta(2p + w), one beta per warp ============
        float* basis = &smem_f[w * 96];          // per-warp slices (96 floats)
        float* C2w   = basis + 64;

        const int   t  = blockIdx.x * 2 + w;
        const float x  = t_steps[t];
        const float dt = t_steps[1] - t_steps[0];

        {   // layer-1 basis: 50 exps (lanes 0..17 do two)
            float d = x - grid1[lane];
            basis[lane] = __expf(-10.0f * d * d);
            if (lane < G1 - 32) {
                float d2 = x - grid1[lane + 32];
                basis[lane + 32] = __expf(-10.0f * d2 * d2);
            }
        }
        if (lane < G2) {
            float v = grid2[lane] - 0.5f;
            C2w[lane] = __expf(-10.0f * v * v);
        }
        __syncwarp();

        // h[lane] = x*base_w1[lane] + sum_g basis[g]*w1[g][lane]  (4 chains)
        float a0 = x * base_w1[lane], a1 = 0.0f, a2 = 0.0f, a3 = 0.0f;
        #pragma unroll
        for (int g = 0; g + 3 < G1; g += 4) {
            a0 = fmaf(basis[g],     spline_w1[g * H1 + lane],       a0);
            a1 = fmaf(basis[g + 1], spline_w1[(g + 1) * H1 + lane], a1);
            a2 = fmaf(basis[g + 2], spline_w1[(g + 2) * H1 + lane], a2);
            a3 = fmaf(basis[g + 3], spline_w1[(g + 3) * H1 + lane], a3);
        }
        a0 = fmaf(basis[48], spline_w1[48 * H1 + lane], a0);   // 48, 49 tail
        a1 = fmaf(basis[49], spline_w1[49 * H1 + lane], a1);
        const float h = (a0 + a1) + (a2 + a3);

        // layer-2 factorized RBF: exp(-10(h-g_k)^2) = e0 * tk * C2[k]
        float u = fminf(fmaxf(h - 0.5f, -2.5f), 2.5f);   // clamp: basis ~0
        const float v0 = grid2[0] - 0.5f;
        const float dv = grid2[1] - grid2[0];
        const float e0 = __expf(-10.0f * u * u);
        float       tk = __expf(20.0f * u * v0);
        const float f  = __expf(20.0f * u * dv);

        float acc = 0.0f;
        #pragma unroll
        for (int k = 0; k < G2; k++) {
            acc = fmaf(tk * C2w[k], spline_w2[lane * G2 + k], acc);
            tk *= f;
        }
        acc = fmaf(h, base_w2[lane], e0 * acc);

        #pragma unroll
        for (int o = 16; o > 0; o >>= 1)
            acc += __shfl_down_sync(0xFFFFFFFFu, acc, o);

        if (lane == 0) {
            float beta = fmaxf(acc, 0.0f) + log1pf(expf(-fabsf(acc)));
            g_cbeta[t] = dt * beta;
        }

        __syncthreads();                    // both warps' betas written
        if (tid == 0) {
            __threadfence();                // publish betas before arrival
            atomicAdd(&g_cnt[(blockIdx.x >> 7) * 32], 1u);  // REDG arrival
        }
        return;
    }

    // ===================== CONSUMER: Euler SIR scan ======================
    const int sbid = blockIdx.x - KAN_BLOCKS;

    __shared__ unsigned int starget;
    if (tid == 0) {
        unsigned int e = g_blkepoch[sbid] + 1u;   // owner-only, race-free
        g_blkepoch[sbid] = e;
        starget = e * PROD_PER_CH;                // monotonic per-chunk target
    }

    // Beta-independent prologue (overlaps producers)
    const int   b      = sbid * 64 + tid;
    const float I_init = initial_I[b];
    const float gp     = gamma_param[0];
    const float dt     = t_steps[1] - t_steps[0];
    const float gamma  = fmaxf(gp, 0.0f) + log1pf(expf(-fabsf(gp)));
    const float a      = 1.0f - dt * gamma;       // I' = I*a + ni

    __syncthreads();                              // starget visible
    const unsigned int tgt = starget;

    float I = I_init;
    float S = 1.0f - I;
    float* outp = out + b;

    #pragma unroll 1
    for (int c = 0; c < NCH; c++) {
        if (tid == 0) {
            while (*((volatile unsigned int*)&g_cnt[c * 32]) < tgt) { }
            __threadfence();                      // acquire betas
        }
        __syncthreads();
        #pragma unroll
        for (int k = 0; k < CH_T / 64; k++)
            smem_f[tid + k * 64] = __ldcg(&g_cbeta[c * CH_T + tid + k * 64]);
        if (tid == 0) smem_f[CH_T] = 0.0f;        // prefetch sentinel
        __syncthreads();

        float* op = outp + (size_t)c * CH_T * B_SIZE;
        float cb = smem_f[0];
        #pragma unroll 8
        for (int u = 0; u < CH_T; u++) {
            const float cbn = smem_f[u + 1];      // prefetch next beta
            const float ni = cb * (S * I);        // dt * new_infections
            I = fmaf(I, a, ni);                   // clips removed: state in [0,1]
            S = S - ni;
            op[(size_t)u * B_SIZE] = I;
            cb = cbn;
        }
        __syncthreads();                          // smem_f reused next chunk
    }
}

// ---------------------------------------------------------------------------
// Inputs (metadata order):
// 0: t_steps [1024], 1: initial_I [32768], 2: grid1 [50], 3: spline_w1 [1600],
// 4: base_w1 [32], 5: grid2 [20], 6: spline_w2 [640], 7: base_w2 [32],
// 8: gamma_param [1]
// ---------------------------------------------------------------------------
extern "C" void kernel_launch(void* const* d_in, const int* in_sizes, int n_in,
                              void* d_out, int out_size)
{
    const float* t_steps    = (const float*)d_in[0];
    const float* initial_I  = (const float*)d_in[1];
    const float* grid1      = (const float*)d_in[2];
    const float* spline_w1  = (const float*)d_in[3];
    const float* base_w1    = (const float*)d_in[4];
    const float* grid2      = (const float*)d_in[5];
    const float* spline_w2  = (const float*)d_in[6];
    const float* base_w2    = (const float*)d_in[7];
    const float* gamma_p    = (const float*)d_in[8];
    float* out              = (float*)d_out;

    fused_role_kernel<<<NBLOCKS, 64>>>(t_steps, initial_I, grid1,
                                       spline_w1, base_w1, grid2,
                                       spline_w2, base_w2, gamma_p, out);
}

// round 15
// speedup vs baseline: 1.0087x; 1.0087x over previous
#include <cuda_runtime.h>
#include <math.h>

// Problem constants (match reference)
#define T_STEPS 1024
#define B_SIZE  32768
#define G1      50
#define H1      32
#define G2      20

#define KAN_BLOCKS 256                  // producers (dispatched first)
#define SIR_BLOCKS 512                  // consumers
#define NBLOCKS    (KAN_BLOCKS + SIR_BLOCKS)

// Device globals (zero-init at load; NEVER reset — monotonic across launches)
__device__ float        g_cbeta[T_STEPS];
__device__ unsigned int g_cnt;                       // producer arrivals
__device__ unsigned int g_blkepoch[SIR_BLOCKS];      // per-consumer epoch

// ---------------------------------------------------------------------------
// Single-kernel role split (identical to R13 except producers use 2-way ILP).
//  Producers (blocks 0..255, dispatched first): warp w computes betas
//    t0 = 4p + 2w and t0+1 INTERLEAVED — the two independent chains share
//    every weight load (spline_w1/spline_w2 fetched once, used twice), so
//    producer latency ~ one chain instead of two.
//    tid0 then fences and RED-arrives on g_cnt (atomicAdd, return unused
//    -> REDG 0.854 cyc/op: no atomic-ALU serialization).
//  Consumers (blocks 256..767): e = ++g_blkepoch[sbid] (owner-only,
//    race-free); beta-independent prologue overlaps producers; spin until
//    g_cnt >= 256*e (monotonic target: stale counter 256(e-1) never
//    passes); then the proven DRAM-write-bound 24.5us Euler scan.
// Deadlock safety: 768 blocks x 64 thr -> whole grid resident in one wave;
// consumers spin only on producers, which never wait.
// ---------------------------------------------------------------------------
__global__ void __launch_bounds__(64)
fused_role_kernel(const float* __restrict__ t_steps,
                  const float* __restrict__ initial_I,
                  const float* __restrict__ grid1,
                  const float* __restrict__ spline_w1, // [50,32]
                  const float* __restrict__ base_w1,   // [32]
                  const float* __restrict__ grid2,
                  const float* __restrict__ spline_w2, // [32,20]
                  const float* __restrict__ base_w2,   // [32]
                  const float* __restrict__ gamma_param,
                  float* __restrict__ out)
{
    __shared__ float smem_f[T_STEPS + 8];   // sir: beta cache | kan: scratch

    const int tid  = threadIdx.x;
    const int w    = tid >> 5;
    const int lane = tid & 31;

    if (blockIdx.x < KAN_BLOCKS) {
        // ========= PRODUCER: betas t0, t0+1 per warp, ILP-interleaved =========
        float* bas0 = &smem_f[w * 160];          // per-warp slices
        float* bas1 = bas0 + 64;
        float* C2w  = bas0 + 128;

        const int   t0 = blockIdx.x * 4 + w * 2;
        const float x0 = t_steps[t0];
        const float x1 = t_steps[t0 + 1];
        const float dt = t_steps[1] - t_steps[0];

        {   // layer-1 bases for both t's (100 exps/warp, independent)
            const float g = grid1[lane];
            float d0 = x0 - g, d1 = x1 - g;
            bas0[lane] = __expf(-10.0f * d0 * d0);
            bas1[lane] = __expf(-10.0f * d1 * d1);
            if (lane < G1 - 32) {
                const float g2v = grid1[lane + 32];
                float e0 = x0 - g2v, e1 = x1 - g2v;
                bas0[lane + 32] = __expf(-10.0f * e0 * e0);
                bas1[lane + 32] = __expf(-10.0f * e1 * e1);
            }
        }
        if (lane < G2) {
            float v = grid2[lane] - 0.5f;
            C2w[lane] = __expf(-10.0f * v * v);
        }
        __syncwarp();

        // h chains for both betas; each weight loaded ONCE, used twice.
        const float bw1 = base_w1[lane];
        float a0 = x0 * bw1, a1 = 0.0f;          // beta0 accumulators
        float c0 = x1 * bw1, c1 = 0.0f;          // beta1 accumulators
        #pragma unroll
        for (int g = 0; g < G1; g += 2) {
            const float wa = spline_w1[g * H1 + lane];
            const float wb = spline_w1[(g + 1) * H1 + lane];
            a0 = fmaf(bas0[g],     wa, a0);
            c0 = fmaf(bas1[g],     wa, c0);
            a1 = fmaf(bas0[g + 1], wb, a1);
            c1 = fmaf(bas1[g + 1], wb, c1);
        }
        const float h0 = a0 + a1;
        const float h1 = c0 + c1;

        // layer-2 factorized RBF for both (6 exps total per lane)
        const float v0 = grid2[0] - 0.5f;
        const float dv = grid2[1] - grid2[0];
        float u0 = fminf(fmaxf(h0 - 0.5f, -2.5f), 2.5f);  // clamp: basis ~0
        float u1 = fminf(fmaxf(h1 - 0.5f, -2.5f), 2.5f);
        const float e00 = __expf(-10.0f * u0 * u0);
        const float e01 = __expf(-10.0f * u1 * u1);
        float tk0 = __expf(20.0f * u0 * v0);
        float tk1 = __expf(20.0f * u1 * v0);
        const float f0 = __expf(20.0f * u0 * dv);
        const float f1 = __expf(20.0f * u1 * dv);

        float s0 = 0.0f, s1 = 0.0f;
        #pragma unroll
        for (int k = 0; k < G2; k++) {
            const float w2 = spline_w2[lane * G2 + k];   // loaded once
            const float ck = C2w[k];
            s0 = fmaf(tk0 * ck, w2, s0);
            s1 = fmaf(tk1 * ck, w2, s1);
            tk0 *= f0;
            tk1 *= f1;
        }
        const float bw2 = base_w2[lane];
        s0 = fmaf(h0, bw2, e00 * s0);
        s1 = fmaf(h1, bw2, e01 * s1);

        #pragma unroll
        for (int o = 16; o > 0; o >>= 1) {
            s0 += __shfl_down_sync(0xFFFFFFFFu, s0, o);
            s1 += __shfl_down_sync(0xFFFFFFFFu, s1, o);
        }

        if (lane == 0) {
            float beta0 = fmaxf(s0, 0.0f) + log1pf(expf(-fabsf(s0)));
            float beta1 = fmaxf(s1, 0.0f) + log1pf(expf(-fabsf(s1)));
            g_cbeta[t0]     = dt * beta0;
            g_cbeta[t0 + 1] = dt * beta1;
        }

        __syncthreads();                    // both warps' betas written
        if (tid == 0) {
            __threadfence();                // publish betas before arrival
            atomicAdd(&g_cnt, 1u);          // return unused -> REDG
        }
        return;
    }

    // ===================== CONSUMER: Euler SIR scan ======================
    const int sbid = blockIdx.x - KAN_BLOCKS;

    __shared__ unsigned int starget;
    if (tid == 0) {
        unsigned int e = g_blkepoch[sbid] + 1u;   // owner-only, race-free
        g_blkepoch[sbid] = e;
        starget = e * KAN_BLOCKS;                 // monotonic counter target
    }

    // Beta-independent prologue (overlaps producers)
    const int   b      = sbid * 64 + tid;
    const float I_init = initial_I[b];
    const float gp     = gamma_param[0];
    const float dt     = t_steps[1] - t_steps[0];
    const float gamma  = fmaxf(gp, 0.0f) + log1pf(expf(-fabsf(gp)));
    const float a      = 1.0f - dt * gamma;       // I' = I*a + ni

    __syncthreads();                              // starget visible
    if (tid == 0) {
        const unsigned int tgt = starget;
        while (*((volatile unsigned int*)&g_cnt) < tgt) { }
        __threadfence();                          // acquire betas
    }
    __syncthreads();

    #pragma unroll
    for (int i = 0; i < T_STEPS / 64; i++)
        smem_f[tid + i * 64] = __ldcg(&g_cbeta[tid + i * 64]);
    if (tid < 8) smem_f[T_STEPS + tid] = 0.0f;    // prefetch sentinel

    float I = I_init;
    float S = 1.0f - I;

    __syncthreads();

    float* outp = out + b;
    float cb = smem_f[0];
    #pragma unroll 8
    for (int t = 0; t < T_STEPS; t++) {
        const float cb_n = smem_f[t + 1];         // prefetch next beta
        const float ni = cb * (S * I);            // dt * new_infections
        I = fmaf(I, a, ni);                       // clips removed: state in [0,1]
        S = S - ni;
        outp[(size_t)t * B_SIZE] = I;
        cb = cb_n;
    }
}

// ---------------------------------------------------------------------------
// Inputs (metadata order):
// 0: t_steps [1024], 1: initial_I [32768], 2: grid1 [50], 3: spline_w1 [1600],
// 4: base_w1 [32], 5: grid2 [20], 6: spline_w2 [640], 7: base_w2 [32],
// 8: gamma_param [1]
// ---------------------------------------------------------------------------
extern "C" void kernel_launch(void* const* d_in, const int* in_sizes, int n_in,
                              void* d_out, int out_size)
{
    const float* t_steps    = (const float*)d_in[0];
    const float* initial_I  = (const float*)d_in[1];
    const float* grid1      = (const float*)d_in[2];
    const float* spline_w1  = (const float*)d_in[3];
    const float* base_w1    = (const float*)d_in[4];
    const float* grid2      = (const float*)d_in[5];
    const float* spline_w2  = (const float*)d_in[6];
    const float* base_w2    = (const float*)d_in[7];
    const float* gamma_p    = (const float*)d_in[8];
    float* out              = (float*)d_out;

    fused_role_kernel<<<NBLOCKS, 64>>>(t_steps, initial_I, grid1,
                                       spline_w1, base_w1, grid2,
                                       spline_w2, base_w2, gamma_p, out);
}

// round 16
// speedup vs baseline: 1.0127x; 1.0039x over previous
#include <cuda_runtime.h>
#include <math.h>

// Problem constants (match reference)
#define T_STEPS 1024
#define B_SIZE  32768
#define G1      50
#define H1      32
#define G2      20

#define KAN_BLOCKS 256                  // producers (dispatched first)
#define SIR_BLOCKS 512                  // consumers
#define NBLOCKS    (KAN_BLOCKS + SIR_BLOCKS)
#define NCH        4                    // graduated beta chunks

// Device globals (zero-init at load; NEVER reset — monotonic across launches)
__device__ float        g_cbeta[T_STEPS];
__device__ unsigned int g_cnt[NCH * 32];             // per-chunk arrivals, 128B apart
__device__ unsigned int g_blkepoch[SIR_BLOCKS];      // per-consumer epoch

// Graduated chunks: steps {128,128,256,512}, producer blocks {32,32,64,128}.
__device__ __constant__ int          c_chlen[NCH]  = {128, 128, 256, 512};
__device__ __constant__ int          c_choff[NCH]  = {0, 128, 256, 512};
__device__ __constant__ unsigned int c_ctgt [NCH]  = {32, 32, 64, 128};

// ---------------------------------------------------------------------------
// Single-kernel role split + graduated chunk pipeline (R13 producer verbatim).
//  Producers (blocks 0..255): each warp computes 2 betas (4 per block:
//    t = 4p + 2w + s), factorized layer-2 RBF, warp-local. tid0 fences and
//    RED-arrives on its chunk counter (return unused -> REDG, no ALU storm).
//    Chunk id: p<32 -> 0, p<64 -> 1, p<128 -> 2, else 3 (beta ranges align
//    with chunk boundaries since they are multiples of 128 = 32 blocks).
//  Consumers (blocks 256..767): e = ++g_blkepoch[sbid] (owner-only);
//    prologue overlaps producers; per chunk c wait g_cnt[c] >= ctgt[c]*e
//    (monotonic epoch target — stale counters never false-pass; no resets).
//    Exposed wait = first 32 producers only (~2us); later chunks are ready
//    before their scan begins (each chunk scan >= 3us).
// Deadlock safety: 768 blocks x 64 thr -> whole grid in one wave; consumers
// spin only on producers, which never wait.
// ---------------------------------------------------------------------------
__global__ void __launch_bounds__(64)
fused_role_kernel(const float* __restrict__ t_steps,
                  const float* __restrict__ initial_I,
                  const float* __restrict__ grid1,
                  const float* __restrict__ spline_w1, // [50,32]
                  const float* __restrict__ base_w1,   // [32]
                  const float* __restrict__ grid2,
                  const float* __restrict__ spline_w2, // [32,20]
                  const float* __restrict__ base_w2,   // [32]
                  const float* __restrict__ gamma_param,
                  float* __restrict__ out)
{
    __shared__ float smem_f[T_STEPS + 8];   // sir: beta cache | kan: scratch

    const int tid  = threadIdx.x;
    const int w    = tid >> 5;
    const int lane = tid & 31;

    if (blockIdx.x < KAN_BLOCKS) {
        // =================== PRODUCER: 4 betas per block ===================
        float* basis = &smem_f[w * 96];          // per-warp slices
        float* C2w   = basis + 64;

        if (lane < G2) {
            float v = grid2[lane] - 0.5f;
            C2w[lane] = __expf(-10.0f * v * v);
        }

        const float dt = t_steps[1] - t_steps[0];

        #pragma unroll
        for (int s = 0; s < 2; s++) {
            const int   t = blockIdx.x * 4 + w * 2 + s;
            const float x = t_steps[t];

            {   // layer-1 basis: 50 exps (lanes 0..17 do two)
                float d = x - grid1[lane];
                basis[lane] = __expf(-10.0f * d * d);
                if (lane < G1 - 32) {
                    float d2 = x - grid1[lane + 32];
                    basis[lane + 32] = __expf(-10.0f * d2 * d2);
                }
            }
            __syncwarp();

            // h[lane] = x*base_w1[lane] + sum_g basis[g]*w1[g][lane]
            float h = x * base_w1[lane];
            #pragma unroll
            for (int g = 0; g < G1; g++)
                h = fmaf(basis[g], spline_w1[g * H1 + lane], h);

            // layer-2 factorized RBF: exp(-10(h-g_k)^2) = e0 * tk * C2[k]
            float u = fminf(fmaxf(h - 0.5f, -2.5f), 2.5f); // clamp: basis ~0
            const float v0 = grid2[0] - 0.5f;
            const float dv = grid2[1] - grid2[0];
            const float e0 = __expf(-10.0f * u * u);
            float       tk = __expf(20.0f * u * v0);
            const float f  = __expf(20.0f * u * dv);

            float acc = 0.0f;
            #pragma unroll
            for (int k = 0; k < G2; k++) {
                acc = fmaf(tk * C2w[k], spline_w2[lane * G2 + k], acc);
                tk *= f;
            }
            acc = fmaf(h, base_w2[lane], e0 * acc);

            #pragma unroll
            for (int o = 16; o > 0; o >>= 1)
                acc += __shfl_down_sync(0xFFFFFFFFu, acc, o);

            if (lane == 0) {
                float beta = fmaxf(acc, 0.0f) + log1pf(expf(-fabsf(acc)));
                g_cbeta[t] = dt * beta;
            }
            __syncwarp();
        }

        __syncthreads();
        if (tid == 0) {
            const int p = blockIdx.x;
            const int c = (p >= 32) + (p >= 64) + (p >= 128); // graduated chunk
            __threadfence();               // publish betas before arrival
            atomicAdd(&g_cnt[c * 32], 1u); // return unused -> REDG
        }
        return;
    }

    // ===================== CONSUMER: Euler SIR scan ======================
    const int sbid = blockIdx.x - KAN_BLOCKS;

    __shared__ unsigned int sepoch;
    if (tid == 0) {
        unsigned int e = g_blkepoch[sbid] + 1u;   // owner-only, race-free
        g_blkepoch[sbid] = e;
        sepoch = e;
    }

    // Beta-independent prologue (overlaps producers)
    const int   b      = sbid * 64 + tid;
    const float I_init = initial_I[b];
    const float gp     = gamma_param[0];
    const float dt     = t_steps[1] - t_steps[0];
    const float gamma  = fmaxf(gp, 0.0f) + log1pf(expf(-fabsf(gp)));
    const float a      = 1.0f - dt * gamma;       // I' = I*a + ni

    __syncthreads();                              // sepoch visible
    const unsigned int e = sepoch;

    float I = I_init;
    float S = 1.0f - I;
    float* outp = out + b;

    #pragma unroll
    for (int c = 0; c < NCH; c++) {
        const int len = c_chlen[c];
        const int off = c_choff[c];
        if (tid == 0) {
            const unsigned int tgt = c_ctgt[c] * e;   // monotonic target
            while (*((volatile unsigned int*)&g_cnt[c * 32]) < tgt) { }
            __threadfence();                          // acquire betas
        }
        __syncthreads();
        for (int k = tid; k < len; k += 64)
            smem_f[k] = __ldcg(&g_cbeta[off + k]);
        if (tid == 0) smem_f[len] = 0.0f;             // prefetch sentinel
        __syncthreads();

        float* op = outp + (size_t)off * B_SIZE;
        float cb = smem_f[0];
        #pragma unroll 8
        for (int u = 0; u < len; u++) {
            const float cbn = smem_f[u + 1];          // prefetch next beta
            const float ni = cb * (S * I);            // dt * new_infections
            I = fmaf(I, a, ni);                       // clips removed: state in [0,1]
            S = S - ni;
            op[(size_t)u * B_SIZE] = I;
            cb = cbn;
        }
        __syncthreads();                              // smem_f reused next chunk
    }
}

// ---------------------------------------------------------------------------
// Inputs (metadata order):
// 0: t_steps [1024], 1: initial_I [32768], 2: grid1 [50], 3: spline_w1 [1600],
// 4: base_w1 [32], 5: grid2 [20], 6: spline_w2 [640], 7: base_w2 [32],
// 8: gamma_param [1]
// ---------------------------------------------------------------------------
extern "C" void kernel_launch(void* const* d_in, const int* in_sizes, int n_in,
                              void* d_out, int out_size)
{
    const float* t_steps    = (const float*)d_in[0];
    const float* initial_I  = (const float*)d_in[1];
    const float* grid1      = (const float*)d_in[2];
    const float* spline_w1  = (const float*)d_in[3];
    const float* base_w1    = (const float*)d_in[4];
    const float* grid2      = (const float*)d_in[5];
    const float* spline_w2  = (const float*)d_in[6];
    const float* base_w2    = (const float*)d_in[7];
    const float* gamma_p    = (const float*)d_in[8];
    float* out              = (float*)d_out;

    fused_role_kernel<<<NBLOCKS, 64>>>(t_steps, initial_I, grid1,
                                       spline_w1, base_w1, grid2,
                                       spline_w2, base_w2, gamma_p, out);
}

// round 17
// speedup vs baseline: 1.0537x; 1.0405x over previous
#include <cuda_runtime.h>
#include <math.h>

// Problem constants (match reference)
#define T_STEPS 1024
#define B_SIZE  32768
#define G1      50
#define H1      32
#define G2      20
#define NBLOCKS 256                     // minimal grid: 256 x 128 threads
#define NTHR    128

// Device globals (zero-init at load; NEVER reset — monotonic across launches)
__device__ float        g_cbeta[T_STEPS];
__device__ unsigned int g_cnt;                     // producer arrivals
__device__ unsigned int g_blkepoch[NBLOCKS];       // per-block launch epoch

// ---------------------------------------------------------------------------
// Single kernel, minimal CTA count (dispatch tail ~1.3us instead of ~4us).
//  Phase 1: warp w (of 4) computes beta(4*bid + w) fully warp-locally
//    (factorized layer-2 RBF: 3 exps/(t,i)). 256 blocks x 4 warps = 1024.
//    tid0 fences + atomicAdd(&g_cnt,1) (return unused -> REDG, no ALU storm).
//  Phase 2: e = ++g_blkepoch[bid] (owner-only, race-free); spin until
//    g_cnt >= 256*e (monotonic epoch target: stale counter 256(e-1) can
//    never false-pass; NO reset logic), load all betas to smem, run the
//    proven DRAM-write-bound Euler scan (128 elems/block).
// Deadlock safety: every block ARRIVES before it waits, and 256 blocks x
// 128 thr (~1.73 blocks/SM) is trivially one resident wave.
// ---------------------------------------------------------------------------
__global__ void __launch_bounds__(NTHR)
fused_kan_sir_kernel(const float* __restrict__ t_steps,
                     const float* __restrict__ initial_I,
                     const float* __restrict__ grid1,
                     const float* __restrict__ spline_w1, // [50,32]
                     const float* __restrict__ base_w1,   // [32]
                     const float* __restrict__ grid2,
                     const float* __restrict__ spline_w2, // [32,20]
                     const float* __restrict__ base_w2,   // [32]
                     const float* __restrict__ gamma_param,
                     float* __restrict__ out)
{
    __shared__ float smem_f[T_STEPS + 8];   // phase1: 4x96 scratch | phase2: betas
    __shared__ unsigned int starget;

    const int tid  = threadIdx.x;
    const int w    = tid >> 5;              // 0..3
    const int lane = tid & 31;

    // ---- Epoch bump + beta-independent prologue (overlaps phase 1) ----
    if (tid == 0) {
        unsigned int e = g_blkepoch[blockIdx.x] + 1u;   // owner-only RMW
        g_blkepoch[blockIdx.x] = e;
        starget = e * (unsigned)NBLOCKS;
    }
    const int   b      = blockIdx.x * NTHR + tid;
    const float I_init = initial_I[b];
    const float gp     = gamma_param[0];
    const float dt     = t_steps[1] - t_steps[0];

    // ---- Phase 1: beta(4*bid + w), one beta per warp, warp-local ----
    {
        float* basis = &smem_f[w * 96];
        float* C2w   = basis + 64;

        const int   t = blockIdx.x * 4 + w;
        const float x = t_steps[t];

        {   // layer-1 basis: 50 exps (lanes 0..17 do two)
            float d = x - grid1[lane];
            basis[lane] = __expf(-10.0f * d * d);
            if (lane < G1 - 32) {
                float d2 = x - grid1[lane + 32];
                basis[lane + 32] = __expf(-10.0f * d2 * d2);
            }
        }
        if (lane < G2) {
            float v = grid2[lane] - 0.5f;
            C2w[lane] = __expf(-10.0f * v * v);
        }
        __syncwarp();

        // h[lane] = x*base_w1[lane] + sum_g basis[g]*w1[g][lane] (2 chains)
        float a0 = x * base_w1[lane], a1 = 0.0f;
        #pragma unroll
        for (int g = 0; g < G1; g += 2) {
            a0 = fmaf(basis[g],     spline_w1[g * H1 + lane],       a0);
            a1 = fmaf(basis[g + 1], spline_w1[(g + 1) * H1 + lane], a1);
        }
        const float h = a0 + a1;

        // layer-2 factorized RBF: exp(-10(h-g_k)^2) = e0 * tk * C2[k]
        float u = fminf(fmaxf(h - 0.5f, -2.5f), 2.5f);   // clamp: basis ~0
        const float v0 = grid2[0] - 0.5f;
        const float dv = grid2[1] - grid2[0];
        const float e0 = __expf(-10.0f * u * u);
        float       tk = __expf(20.0f * u * v0);
        const float f  = __expf(20.0f * u * dv);

        float acc = 0.0f;
        #pragma unroll
        for (int k = 0; k < G2; k++) {
            acc = fmaf(tk * C2w[k], spline_w2[lane * G2 + k], acc);
            tk *= f;
        }
        acc = fmaf(h, base_w2[lane], e0 * acc);

        #pragma unroll
        for (int o = 16; o > 0; o >>= 1)
            acc += __shfl_down_sync(0xFFFFFFFFu, acc, o);

        if (lane == 0) {
            float beta = fmaxf(acc, 0.0f) + log1pf(expf(-fabsf(acc)));
            g_cbeta[t] = dt * beta;
        }
    }

    __syncthreads();                      // all 4 betas written; starget set
    if (tid == 0) {
        __threadfence();                  // publish betas before arrival
        atomicAdd(&g_cnt, 1u);            // return unused -> REDG
    }

    // ---- Wait for all 1024 betas (monotonic epoch target) ----
    if (tid == 0) {
        const unsigned int tgt = starget;
        while (*((volatile unsigned int*)&g_cnt) < tgt) { }
        __threadfence();                  // acquire betas
    }
    __syncthreads();

    // ---- Phase 2: betas -> smem, proven Euler SIR scan ----
    #pragma unroll
    for (int i = 0; i < T_STEPS / NTHR; i++)
        smem_f[tid + i * NTHR] = __ldcg(&g_cbeta[tid + i * NTHR]);
    if (tid < 8) smem_f[T_STEPS + tid] = 0.0f;   // prefetch sentinel

    float I = I_init;
    float S = 1.0f - I;
    const float gamma = fmaxf(gp, 0.0f) + log1pf(expf(-fabsf(gp)));
    const float a     = 1.0f - dt * gamma;       // I' = I*a + ni

    __syncthreads();

    float* outp = out + b;
    float cb = smem_f[0];
    #pragma unroll 8
    for (int t = 0; t < T_STEPS; t++) {
        const float cb_n = smem_f[t + 1];        // prefetch next beta
        const float ni = cb * (S * I);           // dt * new_infections
        I = fmaf(I, a, ni);                      // clips removed: state in [0,1]
        S = S - ni;
        outp[(size_t)t * B_SIZE] = I;
        cb = cb_n;
    }
}

// ---------------------------------------------------------------------------
// Inputs (metadata order):
// 0: t_steps [1024], 1: initial_I [32768], 2: grid1 [50], 3: spline_w1 [1600],
// 4: base_w1 [32], 5: grid2 [20], 6: spline_w2 [640], 7: base_w2 [32],
// 8: gamma_param [1]
// ---------------------------------------------------------------------------
extern "C" void kernel_launch(void* const* d_in, const int* in_sizes, int n_in,
                              void* d_out, int out_size)
{
    const float* t_steps    = (const float*)d_in[0];
    const float* initial_I  = (const float*)d_in[1];
    const float* grid1      = (const float*)d_in[2];
    const float* spline_w1  = (const float*)d_in[3];
    const float* base_w1    = (const float*)d_in[4];
    const float* grid2      = (const float*)d_in[5];
    const float* spline_w2  = (const float*)d_in[6];
    const float* base_w2    = (const float*)d_in[7];
    const float* gamma_p    = (const float*)d_in[8];
    float* out              = (float*)d_out;

    fused_kan_sir_kernel<<<NBLOCKS, NTHR>>>(t_steps, initial_I, grid1,
                                            spline_w1, base_w1, grid2,
                                            spline_w2, base_w2, gamma_p, out);
}